// round 1
// baseline (speedup 1.0000x reference)
#include <cuda_runtime.h>
#include <cstdint>

#define LEN      2048
#define BM       128      // query rows per CTA
#define BN       64       // kv rows per tile
#define NKV      (LEN / BN)
#define NTHREADS 256
#define NWARP    8

// smem strides (floats), padded against bank conflicts
#define SQ_STRIDE 132     // sQ: [64 c][132]   (holds 128 t values)
#define SK_STRIDE 68      // sK/sV: [64 c][68] (holds 64 values)
#define SP_STRIDE 68      // sP per warp: [16 t][68] (holds 64 s values)

#define SQ_SIZE (64 * SQ_STRIDE)     // 8448 floats
#define SK_SIZE (64 * SK_STRIDE)     // 4352 floats
#define SP_SIZE (16 * SP_STRIDE)     // 1088 floats per warp

// total: sQ + 2*sK + 2*sV + 8*sP
#define SMEM_FLOATS (SQ_SIZE + 4 * SK_SIZE + NWARP * SP_SIZE)
#define SMEM_BYTES  (SMEM_FLOATS * 4)   // 138240 B

__device__ __forceinline__ uint32_t f2tf32(float f) {
    uint32_t u;
    asm("cvt.rna.tf32.f32 %0, %1;" : "=r"(u) : "f"(f));
    return u;
}

__device__ __forceinline__ float ex2f(float x) {
    float y;
    asm("ex2.approx.ftz.f32 %0, %1;" : "=f"(y) : "f"(x));
    return y;
}

__device__ __forceinline__ void mma_tf32(float c[4], const uint32_t a[4],
                                         uint32_t b0, uint32_t b1) {
    asm volatile(
        "mma.sync.aligned.m16n8k8.row.col.f32.tf32.tf32.f32 "
        "{%0,%1,%2,%3}, {%4,%5,%6,%7}, {%8,%9}, {%0,%1,%2,%3};"
        : "+f"(c[0]), "+f"(c[1]), "+f"(c[2]), "+f"(c[3])
        : "r"(a[0]), "r"(a[1]), "r"(a[2]), "r"(a[3]), "r"(b0), "r"(b1));
}

__device__ __forceinline__ void cp_async16(uint32_t dst, const void* src) {
    asm volatile("cp.async.cg.shared.global [%0], [%1], 16;" :: "r"(dst), "l"(src));
}

__device__ __forceinline__ void cp_commit() {
    asm volatile("cp.async.commit_group;" ::: "memory");
}

__device__ __forceinline__ void cp_wait_all() {
    asm volatile("cp.async.wait_group 0;" ::: "memory");
}

__global__ void __launch_bounds__(NTHREADS, 1)
attn_tf32_kernel(const float* __restrict__ qkv, float* __restrict__ out)
{
    const int qt   = blockIdx.x;          // 0..15 query tile
    const int bh   = blockIdx.y;          // 0..31 batch*head
    const int b    = bh >> 3;
    const int h    = bh & 7;
    const int tid  = threadIdx.x;
    const int warp = tid >> 5;
    const int lane = tid & 31;
    const int g    = lane >> 2;           // 0..7
    const int quad = lane & 3;            // 0..3

    // qkv: [4][1536][2048]; per head: 192 channels (64 q, 64 k, 64 v)
    const float* qbase = qkv + ((size_t)b * 1536 + (size_t)h * 192) * LEN;
    const float* kbase = qbase + (size_t)64 * LEN;
    const float* vbase = qbase + (size_t)128 * LEN;
    const int t0 = qt * BM;

    extern __shared__ float smem[];
    float* sQ = smem;
    float* sK = smem + SQ_SIZE;
    float* sV = sK + 2 * SK_SIZE;
    float* sP = sV + 2 * SK_SIZE;

    const uint32_t sQ_u = (uint32_t)__cvta_generic_to_shared(sQ);
    const uint32_t sK_u = (uint32_t)__cvta_generic_to_shared(sK);
    const uint32_t sV_u = (uint32_t)__cvta_generic_to_shared(sV);

    // ---- prologue: async-load Q tile + K/V tile 0 ----
    #pragma unroll
    for (int j = 0; j < 8; ++j) {               // Q: 2048 float4
        int i = tid + j * NTHREADS;
        int c = i >> 5, f = i & 31;
        cp_async16(sQ_u + (uint32_t)(c * SQ_STRIDE + f * 4) * 4,
                   qbase + (size_t)c * LEN + t0 + f * 4);
    }
    #pragma unroll
    for (int j = 0; j < 4; ++j) {               // K tile 0: 1024 float4
        int i = tid + j * NTHREADS;
        int c = i >> 4, f = i & 15;
        cp_async16(sK_u + (uint32_t)(c * SK_STRIDE + f * 4) * 4,
                   kbase + (size_t)c * LEN + f * 4);
    }
    #pragma unroll
    for (int j = 0; j < 4; ++j) {               // V tile 0
        int i = tid + j * NTHREADS;
        int c = i >> 4, f = i & 15;
        cp_async16(sV_u + (uint32_t)(c * SK_STRIDE + f * 4) * 4,
                   vbase + (size_t)c * LEN + f * 4);
    }
    cp_commit();

    // softmax scale folded into Q, in log2 domain for ex2
    const float qscale = 0.125f * 1.44269504088896340736f;

    // per-thread state: rows (warp*16 + g) and (+8)
    float m0 = -1e30f, m1 = -1e30f, l0 = 0.f, l1 = 0.f;
    float o[8][4];
    #pragma unroll
    for (int n = 0; n < 8; ++n)
        #pragma unroll
        for (int r = 0; r < 4; ++r) o[n][r] = 0.f;

    uint32_t qa[8][4];

    for (int it = 0; it < NKV; ++it) {
        cp_wait_all();
        __syncthreads();

        if (it == 0) {
            // Q A-fragments: a0=(t=g, c=quad) a1=(t=g+8) a2=(c=quad+4) a3=(both)
            const int tA = warp * 16 + g;
            #pragma unroll
            for (int k = 0; k < 8; ++k) {
                int c0 = k * 8 + quad;
                qa[k][0] = f2tf32(sQ[c0 * SQ_STRIDE + tA] * qscale);
                qa[k][1] = f2tf32(sQ[c0 * SQ_STRIDE + tA + 8] * qscale);
                qa[k][2] = f2tf32(sQ[(c0 + 4) * SQ_STRIDE + tA] * qscale);
                qa[k][3] = f2tf32(sQ[(c0 + 4) * SQ_STRIDE + tA + 8] * qscale);
            }
        }

        // prefetch next K/V tile into the other buffer
        if (it + 1 < NKV) {
            const int s1 = (it + 1) * BN;
            const uint32_t koff = sK_u + (uint32_t)((it + 1) & 1) * SK_SIZE * 4;
            const uint32_t voff = sV_u + (uint32_t)((it + 1) & 1) * SK_SIZE * 4;
            #pragma unroll
            for (int j = 0; j < 4; ++j) {
                int i = tid + j * NTHREADS;
                int c = i >> 4, f = i & 15;
                cp_async16(koff + (uint32_t)(c * SK_STRIDE + f * 4) * 4,
                           kbase + (size_t)c * LEN + s1 + f * 4);
            }
            #pragma unroll
            for (int j = 0; j < 4; ++j) {
                int i = tid + j * NTHREADS;
                int c = i >> 4, f = i & 15;
                cp_async16(voff + (uint32_t)(c * SK_STRIDE + f * 4) * 4,
                           vbase + (size_t)c * LEN + s1 + f * 4);
            }
            cp_commit();
        }

        const float* kb = sK + (it & 1) * SK_SIZE;
        const float* vb = sV + (it & 1) * SK_SIZE;

        // ---- S = (Q*scale) @ K : 16 rows x 64 kv per warp ----
        float sc[8][4];
        #pragma unroll
        for (int n = 0; n < 8; ++n)
            #pragma unroll
            for (int r = 0; r < 4; ++r) sc[n][r] = 0.f;

        #pragma unroll
        for (int k = 0; k < 8; ++k) {
            #pragma unroll
            for (int n = 0; n < 8; ++n) {
                // B[c][s]: b0=(c=k8+quad, s=n8+g), b1=(c+4)
                uint32_t b0 = f2tf32(kb[(k * 8 + quad) * SK_STRIDE + n * 8 + g]);
                uint32_t b1 = f2tf32(kb[(k * 8 + quad + 4) * SK_STRIDE + n * 8 + g]);
                mma_tf32(sc[n], qa[k], b0, b1);
            }
        }

        // ---- online softmax (log2 domain) ----
        float tm0 = -1e30f, tm1 = -1e30f;
        #pragma unroll
        for (int n = 0; n < 8; ++n) {
            tm0 = fmaxf(tm0, fmaxf(sc[n][0], sc[n][1]));
            tm1 = fmaxf(tm1, fmaxf(sc[n][2], sc[n][3]));
        }
        tm0 = fmaxf(tm0, __shfl_xor_sync(0xffffffffu, tm0, 1));
        tm0 = fmaxf(tm0, __shfl_xor_sync(0xffffffffu, tm0, 2));
        tm1 = fmaxf(tm1, __shfl_xor_sync(0xffffffffu, tm1, 1));
        tm1 = fmaxf(tm1, __shfl_xor_sync(0xffffffffu, tm1, 2));

        const float mn0 = fmaxf(m0, tm0);
        const float mn1 = fmaxf(m1, tm1);
        const float al0 = ex2f(m0 - mn0);
        const float al1 = ex2f(m1 - mn1);
        m0 = mn0; m1 = mn1;

        float ps0 = 0.f, ps1 = 0.f;
        #pragma unroll
        for (int n = 0; n < 8; ++n) {
            sc[n][0] = ex2f(sc[n][0] - mn0);
            sc[n][1] = ex2f(sc[n][1] - mn0);
            sc[n][2] = ex2f(sc[n][2] - mn1);
            sc[n][3] = ex2f(sc[n][3] - mn1);
            ps0 += sc[n][0] + sc[n][1];
            ps1 += sc[n][2] + sc[n][3];
        }
        l0 = l0 * al0 + ps0;
        l1 = l1 * al1 + ps1;

        #pragma unroll
        for (int n = 0; n < 8; ++n) {
            o[n][0] *= al0; o[n][1] *= al0;
            o[n][2] *= al1; o[n][3] *= al1;
        }

        // ---- P: C-frag layout -> smem -> A-frag layout ----
        float* pw = sP + warp * SP_SIZE;
        #pragma unroll
        for (int n = 0; n < 8; ++n) {
            pw[g * SP_STRIDE + n * 8 + quad * 2]           = sc[n][0];
            pw[g * SP_STRIDE + n * 8 + quad * 2 + 1]       = sc[n][1];
            pw[(g + 8) * SP_STRIDE + n * 8 + quad * 2]     = sc[n][2];
            pw[(g + 8) * SP_STRIDE + n * 8 + quad * 2 + 1] = sc[n][3];
        }
        __syncwarp();

        // ---- O += P @ V^T : k-dim is kv(s), n-dim is d ----
        #pragma unroll
        for (int k = 0; k < 8; ++k) {
            uint32_t pa[4];
            pa[0] = f2tf32(pw[g * SP_STRIDE + k * 8 + quad]);
            pa[1] = f2tf32(pw[(g + 8) * SP_STRIDE + k * 8 + quad]);
            pa[2] = f2tf32(pw[g * SP_STRIDE + k * 8 + quad + 4]);
            pa[3] = f2tf32(pw[(g + 8) * SP_STRIDE + k * 8 + quad + 4]);
            #pragma unroll
            for (int n = 0; n < 8; ++n) {
                // B[s][d] = v[d][s]: b0=(s=k8+quad, d=n8+g), b1=(s+4)
                uint32_t b0 = f2tf32(vb[(n * 8 + g) * SK_STRIDE + k * 8 + quad]);
                uint32_t b1 = f2tf32(vb[(n * 8 + g) * SK_STRIDE + k * 8 + quad + 4]);
                mma_tf32(o[n], pa, b0, b1);
            }
        }
        __syncwarp();
    }

    // ---- finalize: reduce l across the quad, normalize, store ----
    l0 += __shfl_xor_sync(0xffffffffu, l0, 1);
    l0 += __shfl_xor_sync(0xffffffffu, l0, 2);
    l1 += __shfl_xor_sync(0xffffffffu, l1, 1);
    l1 += __shfl_xor_sync(0xffffffffu, l1, 2);
    const float inv0 = 1.f / l0;
    const float inv1 = 1.f / l1;

    // out: [b][h*64 + d][t]
    float* obase = out + ((size_t)b * 512 + (size_t)h * 64) * LEN + t0 + warp * 16;
    #pragma unroll
    for (int n = 0; n < 8; ++n) {
        const int d0 = n * 8 + quad * 2;
        obase[(size_t)d0 * LEN + g]           = o[n][0] * inv0;
        obase[(size_t)(d0 + 1) * LEN + g]     = o[n][1] * inv0;
        obase[(size_t)d0 * LEN + g + 8]       = o[n][2] * inv1;
        obase[(size_t)(d0 + 1) * LEN + g + 8] = o[n][3] * inv1;
    }
}

extern "C" void kernel_launch(void* const* d_in, const int* in_sizes, int n_in,
                              void* d_out, int out_size) {
    const float* qkv = (const float*)d_in[0];
    float* out = (float*)d_out;

    cudaFuncSetAttribute(attn_tf32_kernel,
                         cudaFuncAttributeMaxDynamicSharedMemorySize, SMEM_BYTES);

    dim3 grid(LEN / BM, 32);
    attn_tf32_kernel<<<grid, NTHREADS, SMEM_BYTES>>>(qkv, out);
}